// round 17
// baseline (speedup 1.0000x reference)
#include <cuda_runtime.h>
#include <cuda_bf16.h>
#include <mma.h>
#include <math.h>

using namespace nvcuda;

#define NN 50000
#define MP 50048   // padded rows: 391 * 128
#define NE 800000
#define NB1 196    // ceil(NN/256)
#define NBC 6250   // aggC grid = NN*32/256
#define TGA_SMEM 61440

// ---------------- scratch ----------------
static __device__ int   d_cnt[NN];
static __device__ int   d_rowptr[NN + 1];
static __device__ int   d_cursor[NN];
static __device__ int   d_csrc[NE];
static __device__ int   d_part[256];
static __device__ float d_xp[(size_t)NN * 32];
static __device__ unsigned int d_mxh[(size_t)MP * 32];    // [mean21|x21|0] bf16x2
static __device__ __nv_bfloat16 d_wc1h[256 * 64];
static __device__ unsigned int d_h1h[(size_t)MP * 128];   // h1 bf16x2
static __device__ __nv_bfloat16 d_wc2h[256 * 256];
static __device__ float d_pq2[(size_t)MP * 256];          // q half (128..255) fp32
static __device__ unsigned int d_p2h[(size_t)MP * 64];    // p bf16x2
static __device__ unsigned int d_h2h[(size_t)MP * 64];    // h2 bf16x2
static __device__ __nv_bfloat16 d_wc3h[128 * 128];
static __device__ float d_pq3[(size_t)MP * 128];          // q half (64..127) fp32
static __device__ unsigned int d_p3h[(size_t)MP * 32];    // layer-3 p bf16x2
static __device__ float d_h3[(size_t)MP * 64];
static __device__ float d_w1p[128 * 64];
static __device__ float d_m1[256 * 13 * 11 * 11];
static __device__ __nv_bfloat16 d_xcolh[(size_t)896 * 6912];
static __device__ __nv_bfloat16 d_k2h[(size_t)128 * 6912];
static __device__ float d_cg[896 * 128];
static __device__ float d_m2[128 * 891];
static __device__ float d_wmpart[8][64];
static __device__ float d_mnorm[64];
static __device__ float d_rvec[64];
static __device__ float d_pmin[NBC];
static __device__ float d_pmax[NBC];
static __device__ float d_hstats[4];
static __device__ int   d_koff[6912];
static __device__ int   d_poff[896];

// ---------------- merged weight packing + im2col tables ----------------
__global__ void k_packAll(const float* __restrict__ Wl1, const float* __restrict__ Wr1,
                          const float* __restrict__ Wl2, const float* __restrict__ Wr2,
                          const float* __restrict__ Wl3, const float* __restrict__ Wr3,
                          const float* __restrict__ W1) {
    int i = blockIdx.x * blockDim.x + threadIdx.x;
    if (i < 16384) {
        int n = i / 64, f = i % 64;
        float v = 0.f;
        if (f < 21) v = Wl1[n * 21 + f];
        else if (f < 42) v = Wr1[n * 21 + (f - 21)];
        d_wc1h[i] = __float2bfloat16(v);
    } else if (i < 81920) {
        int j = i - 16384;
        int n = j / 256, f = j % 256;
        float v = (n < 128) ? Wl2[n * 256 + f] : Wr2[(n - 128) * 256 + f];
        d_wc2h[j] = __float2bfloat16(v);
    } else if (i < 98304) {
        int j = i - 81920;
        int n = j / 128, f = j % 128;
        float v = (n < 64) ? Wl3[n * 128 + f] : Wr3[(n - 64) * 128 + f];
        d_wc3h[j] = __float2bfloat16(v);
    } else if (i < 106496) {
        int j = i - 98304;
        int n = j / 64;
        d_w1p[j] = (n < 64) ? W1[j] : 0.f;
    } else if (i < 113408) {
        int j = i - 106496;
        int ic = j / 27, tap = j % 27;
        int kd = tap / 9, r = tap % 9, kh = r / 3, kw = r % 3;
        d_koff[j] = ic * 1573 + kd * 121 + kh * 11 + kw;
    } else if (i < 114304) {
        int j = i - 113408;
        int v = 0;
        if (j < 891) {
            int od = j / 81, r2 = j % 81, oh = r2 / 9, ow = r2 % 9;
            v = od * 121 + oh * 11 + ow;
        }
        d_poff[j] = v;
    }
}
__global__ void k_packK2(const float* __restrict__ k2) {
    int i = blockIdx.x * blockDim.x + threadIdx.x;
    if (i < 128 * 6912) d_k2h[i] = __float2bfloat16(k2[i]);
}

// ---------------- CSR build (xpad fused) ----------------
__global__ void k_degcnt(const int* __restrict__ ei, const float* __restrict__ x) {
    int e = blockIdx.x * blockDim.x + threadIdx.x;
    if (e < NE) atomicAdd(&d_cnt[ei[NE + e]], 1);
    if (e < NN * 32) {
        int n = e >> 5, f = e & 31;
        d_xp[e] = (f < 21) ? x[n * 21 + f] : 0.f;
    }
}
__global__ void k_scan1() {
    __shared__ int sh[256];
    int t = threadIdx.x;
    int i = blockIdx.x * 256 + t;
    int v = (i < NN) ? d_cnt[i] : 0;
    sh[t] = v;
    __syncthreads();
#pragma unroll
    for (int off = 1; off < 256; off <<= 1) {
        int a = (t >= off) ? sh[t - off] : 0;
        __syncthreads();
        sh[t] += a;
        __syncthreads();
    }
    if (i < NN) d_rowptr[i] = sh[t] - v;
    if (t == 255) d_part[blockIdx.x] = sh[255];
}
__global__ void k_scan3() {
    __shared__ int sh[256];
    int t = threadIdx.x;
    int v = (t < NB1) ? d_part[t] : 0;
    sh[t] = v;
    __syncthreads();
#pragma unroll
    for (int off = 1; off < 256; off <<= 1) {
        int a = (t >= off) ? sh[t - off] : 0;
        __syncthreads();
        sh[t] += a;
        __syncthreads();
    }
    int base = (blockIdx.x > 0) ? sh[blockIdx.x - 1] : 0;
    int i = blockIdx.x * 256 + t;
    if (i < NN) {
        int r = d_rowptr[i] + base;
        d_rowptr[i] = r;
        d_cursor[i] = r;
    }
    if (i == 0) d_rowptr[NN] = NE;
}
__global__ void k_scatter(const int* __restrict__ ei) {
    int e = blockIdx.x * blockDim.x + threadIdx.x;
    if (e >= NE) return;
    int s = ei[e], d = ei[NE + e];
    int pos = atomicAdd(&d_cursor[d], 1);
    d_csrc[pos] = s;
}

// ---------------- aggregation ----------------
__global__ void k_aggA() {
    __shared__ float st[8][64];
    int warp = threadIdx.x >> 5;
    int w = (blockIdx.x * blockDim.x + threadIdx.x) >> 5;
    int lane = threadIdx.x & 31;
    int sub = lane >> 3;
    int sl = lane & 7;
    if (w >= NN) return;
    int beg = d_rowptr[w], end = d_rowptr[w + 1];
    float4 acc = make_float4(0.f, 0.f, 0.f, 0.f);
#pragma unroll 2
    for (int e = beg + sub; e < end; e += 4) {
        int s = __ldg(&d_csrc[e]);
        float4 v = *(const float4*)&d_xp[(size_t)s * 32 + sl * 4];
        acc.x += v.x; acc.y += v.y; acc.z += v.z; acc.w += v.w;
    }
    acc.x += __shfl_xor_sync(0xffffffffu, acc.x, 8);
    acc.y += __shfl_xor_sync(0xffffffffu, acc.y, 8);
    acc.z += __shfl_xor_sync(0xffffffffu, acc.z, 8);
    acc.w += __shfl_xor_sync(0xffffffffu, acc.w, 8);
    acc.x += __shfl_xor_sync(0xffffffffu, acc.x, 16);
    acc.y += __shfl_xor_sync(0xffffffffu, acc.y, 16);
    acc.z += __shfl_xor_sync(0xffffffffu, acc.z, 16);
    acc.w += __shfl_xor_sync(0xffffffffu, acc.w, 16);
    float inv = 1.f / fmaxf((float)(end - beg), 1.0f);
    float* row = st[warp];
    if (sub == 0) {
        float m[4] = {acc.x * inv, acc.y * inv, acc.z * inv, acc.w * inv};
#pragma unroll
        for (int c = 0; c < 4; c++) {
            int f = sl * 4 + c;
            if (f < 21) row[f] = m[c];
        }
    }
    float xo = d_xp[(size_t)w * 32 + lane];
    if (lane < 21) row[21 + lane] = xo;
    if (lane < 22) row[42 + lane] = 0.f;
    __syncwarp();
    if (lane < 16) {
        const float* rp = row + lane * 4;
        __nv_bfloat162 h0 = __floats2bfloat162_rn(rp[0], rp[1]);
        __nv_bfloat162 h1 = __floats2bfloat162_rn(rp[2], rp[3]);
        ((uint2*)d_mxh)[(size_t)w * 16 + lane] =
            make_uint2(*(unsigned int*)&h0, *(unsigned int*)&h1);
    }
}
__global__ void k_aggB(const float* __restrict__ bl) {
    int w = (blockIdx.x * blockDim.x + threadIdx.x) >> 5;
    int lane = threadIdx.x & 31;
    int half = lane >> 4;
    int sl = lane & 15;
    if (w >= NN) return;
    int beg = d_rowptr[w], end = d_rowptr[w + 1];
    float4 a0 = make_float4(0.f, 0.f, 0.f, 0.f);
    float4 a1 = make_float4(0.f, 0.f, 0.f, 0.f);
#pragma unroll 2
    for (int e = beg + half; e < end; e += 2) {
        int s = __ldg(&d_csrc[e]);
        uint4 v = *(const uint4*)&d_p2h[(size_t)s * 64 + sl * 4];
        float2 f0 = __bfloat1622float2(*(__nv_bfloat162*)&v.x);
        float2 f1 = __bfloat1622float2(*(__nv_bfloat162*)&v.y);
        float2 f2 = __bfloat1622float2(*(__nv_bfloat162*)&v.z);
        float2 f3 = __bfloat1622float2(*(__nv_bfloat162*)&v.w);
        a0.x += f0.x; a0.y += f0.y; a0.z += f1.x; a0.w += f1.y;
        a1.x += f2.x; a1.y += f2.y; a1.z += f3.x; a1.w += f3.y;
    }
    a0.x += __shfl_xor_sync(0xffffffffu, a0.x, 16);
    a0.y += __shfl_xor_sync(0xffffffffu, a0.y, 16);
    a0.z += __shfl_xor_sync(0xffffffffu, a0.z, 16);
    a0.w += __shfl_xor_sync(0xffffffffu, a0.w, 16);
    a1.x += __shfl_xor_sync(0xffffffffu, a1.x, 16);
    a1.y += __shfl_xor_sync(0xffffffffu, a1.y, 16);
    a1.z += __shfl_xor_sync(0xffffffffu, a1.z, 16);
    a1.w += __shfl_xor_sync(0xffffffffu, a1.w, 16);
    if (half == 0) {
        float inv = 1.f / fmaxf((float)(end - beg), 1.0f);
        const float4* pq = (const float4*)d_pq2;
        float4 q0 = pq[(size_t)w * 64 + 32 + sl * 2];
        float4 q1 = pq[(size_t)w * 64 + 32 + sl * 2 + 1];
        float4 b0 = ((const float4*)bl)[sl * 2];
        float4 b1 = ((const float4*)bl)[sl * 2 + 1];
        float o[8];
        o[0] = fmaxf(a0.x * inv + b0.x + q0.x, 0.f);
        o[1] = fmaxf(a0.y * inv + b0.y + q0.y, 0.f);
        o[2] = fmaxf(a0.z * inv + b0.z + q0.z, 0.f);
        o[3] = fmaxf(a0.w * inv + b0.w + q0.w, 0.f);
        o[4] = fmaxf(a1.x * inv + b1.x + q1.x, 0.f);
        o[5] = fmaxf(a1.y * inv + b1.y + q1.y, 0.f);
        o[6] = fmaxf(a1.z * inv + b1.z + q1.z, 0.f);
        o[7] = fmaxf(a1.w * inv + b1.w + q1.w, 0.f);
        unsigned int u[4];
#pragma unroll
        for (int t = 0; t < 4; t++) {
            __nv_bfloat162 h = __floats2bfloat162_rn(o[2 * t], o[2 * t + 1]);
            u[t] = *(unsigned int*)&h;
        }
        *(uint4*)&d_h2h[(size_t)w * 64 + sl * 4] = make_uint4(u[0], u[1], u[2], u[3]);
    }
}
// warp per node; 8 lanes per edge (uint4 = 8 bf16 feats), 4 edges in flight
__global__ void k_aggC(const float* __restrict__ bl) {
    __shared__ float smn[256], smx[256];
    int tid = threadIdx.x;
    int w = (blockIdx.x * 256 + tid) >> 5;
    int lane = tid & 31;
    int sub = lane >> 3;
    int sl = lane & 7;
    float lmn = 3.4e38f, lmx = -3.4e38f;
    if (w < NN) {
        int beg = d_rowptr[w], end = d_rowptr[w + 1];
        float4 a0 = make_float4(0.f, 0.f, 0.f, 0.f);
        float4 a1 = make_float4(0.f, 0.f, 0.f, 0.f);
#pragma unroll 2
        for (int e = beg + sub; e < end; e += 4) {
            int s = __ldg(&d_csrc[e]);
            uint4 v = *(const uint4*)&d_p3h[(size_t)s * 32 + sl * 4];
            float2 f0 = __bfloat1622float2(*(__nv_bfloat162*)&v.x);
            float2 f1 = __bfloat1622float2(*(__nv_bfloat162*)&v.y);
            float2 f2 = __bfloat1622float2(*(__nv_bfloat162*)&v.z);
            float2 f3 = __bfloat1622float2(*(__nv_bfloat162*)&v.w);
            a0.x += f0.x; a0.y += f0.y; a0.z += f1.x; a0.w += f1.y;
            a1.x += f2.x; a1.y += f2.y; a1.z += f3.x; a1.w += f3.y;
        }
#pragma unroll
        for (int d = 8; d <= 16; d <<= 1) {
            a0.x += __shfl_xor_sync(0xffffffffu, a0.x, d);
            a0.y += __shfl_xor_sync(0xffffffffu, a0.y, d);
            a0.z += __shfl_xor_sync(0xffffffffu, a0.z, d);
            a0.w += __shfl_xor_sync(0xffffffffu, a0.w, d);
            a1.x += __shfl_xor_sync(0xffffffffu, a1.x, d);
            a1.y += __shfl_xor_sync(0xffffffffu, a1.y, d);
            a1.z += __shfl_xor_sync(0xffffffffu, a1.z, d);
            a1.w += __shfl_xor_sync(0xffffffffu, a1.w, d);
        }
        if (sub == 0) {
            float inv = 1.f / fmaxf((float)(end - beg), 1.0f);
            const float4* pq = (const float4*)d_pq3;
            float4 q0 = pq[(size_t)w * 32 + 16 + sl * 2];
            float4 q1 = pq[(size_t)w * 32 + 16 + sl * 2 + 1];
            float4 b0 = ((const float4*)bl)[sl * 2];
            float4 b1 = ((const float4*)bl)[sl * 2 + 1];
            float4 o0, o1;
            o0.x = a0.x * inv + b0.x + q0.x;
            o0.y = a0.y * inv + b0.y + q0.y;
            o0.z = a0.z * inv + b0.z + q0.z;
            o0.w = a0.w * inv + b0.w + q0.w;
            o1.x = a1.x * inv + b1.x + q1.x;
            o1.y = a1.y * inv + b1.y + q1.y;
            o1.z = a1.z * inv + b1.z + q1.z;
            o1.w = a1.w * inv + b1.w + q1.w;
            ((float4*)d_h3)[(size_t)w * 16 + sl * 2] = o0;
            ((float4*)d_h3)[(size_t)w * 16 + sl * 2 + 1] = o1;
            lmn = fminf(fminf(fminf(o0.x, o0.y), fminf(o0.z, o0.w)),
                        fminf(fminf(o1.x, o1.y), fminf(o1.z, o1.w)));
            lmx = fmaxf(fmaxf(fmaxf(o0.x, o0.y), fmaxf(o0.z, o0.w)),
                        fmaxf(fmaxf(o1.x, o1.y), fmaxf(o1.z, o1.w)));
        }
    }
    smn[tid] = lmn; smx[tid] = lmx;
    __syncthreads();
    for (int st = 128; st > 0; st >>= 1) {
        if (tid < st) {
            smn[tid] = fminf(smn[tid], smn[tid + st]);
            smx[tid] = fmaxf(smx[tid], smx[tid + st]);
        }
        __syncthreads();
    }
    if (tid == 0) { d_pmin[blockIdx.x] = smn[0]; d_pmax[blockIdx.x] = smx[0]; }
}

#define CPA(dst, src) \
    asm volatile("cp.async.cg.shared.global [%0], [%1], 16;" :: "r"(dst), "l"(src))
#define CPCOMMIT() asm volatile("cp.async.commit_group;" ::: "memory")
#define CPWAIT1() asm volatile("cp.async.wait_group 1;" ::: "memory")
#define CPWAIT0() asm volatile("cp.async.wait_group 0;" ::: "memory")

// ---------------- cp.async tf32 GEMM (fp32 in): GEMM4 + fused head ----------
__global__ void __launch_bounds__(256, 2) k_tgemmA(
    const float* __restrict__ A, const float* __restrict__ B, float* __restrict__ C,
    int N, int K, const float* __restrict__ bias, int mode,
    const float* __restrict__ W2p, const float* __restrict__ b2p) {
    extern __shared__ float sm[];
    float* Asm = sm;
    float* Bsm = sm + 3 * 2560;
    int tid = threadIdx.x;
    int wid = tid >> 5;
    int bm = blockIdx.y * 128;
    int bn = blockIdx.x * 128;
    int wm = (wid >> 2) * 64;
    int wn = (wid & 3) * 32;
    int lrow = tid >> 1;
    int lcol = (tid & 1) * 8;
    int nkz = K / 16;

    const float* Ap = A + (size_t)(bm + lrow) * K + lcol;
    const float* Bp = B + (size_t)(bn + lrow) * K + lcol;
    unsigned aS = (unsigned)__cvta_generic_to_shared(Asm + lrow * 20 + lcol);
    unsigned bS = (unsigned)__cvta_generic_to_shared(Bsm + lrow * 20 + lcol);

#define ISSUE(s, koff)                                      \
    do {                                                    \
        unsigned _ao = aS + (s) * 10240;                    \
        unsigned _bo = bS + (s) * 10240;                    \
        CPA(_ao, Ap + (koff)); CPA(_ao + 16, Ap + (koff) + 4); \
        CPA(_bo, Bp + (koff)); CPA(_bo + 16, Bp + (koff) + 4); \
    } while (0)

    wmma::fragment<wmma::accumulator, 16, 16, 8, float> cf[4][2];
#pragma unroll
    for (int i = 0; i < 4; i++)
#pragma unroll
        for (int j = 0; j < 2; j++) wmma::fill_fragment(cf[i][j], 0.f);

    ISSUE(0, 0); CPCOMMIT();
    if (nkz > 1) { ISSUE(1, 16); CPCOMMIT(); }
    else CPCOMMIT();

    for (int it = 0; it < nkz; it++) {
        CPWAIT1();
        __syncthreads();
        if (it + 2 < nkz) ISSUE((it + 2) % 3, (it + 2) * 16);
        CPCOMMIT();
        int buf = it % 3;
        float* Ab = Asm + buf * 2560;
        float* Bb = Bsm + buf * 2560;
#pragma unroll
        for (int ks = 0; ks < 16; ks += 8) {
            wmma::fragment<wmma::matrix_a, 16, 16, 8, wmma::precision::tf32, wmma::row_major> af[4];
            wmma::fragment<wmma::matrix_b, 16, 16, 8, wmma::precision::tf32, wmma::col_major> bf[2];
#pragma unroll
            for (int i = 0; i < 4; i++)
                wmma::load_matrix_sync(af[i], Ab + (wm + i * 16) * 20 + ks, 20);
#pragma unroll
            for (int j = 0; j < 2; j++)
                wmma::load_matrix_sync(bf[j], Bb + (wn + j * 16) * 20 + ks, 20);
#pragma unroll
            for (int i = 0; i < 4; i++)
#pragma unroll
                for (int j = 0; j < 2; j++)
                    wmma::mma_sync(cf[i][j], af[i], bf[j], cf[i][j]);
        }
    }
    CPWAIT0();
    __syncthreads();

    if (mode == 0) {
#pragma unroll
        for (int i = 0; i < 4; i++)
#pragma unroll
            for (int j = 0; j < 2; j++)
                wmma::store_matrix_sync(&C[(size_t)(bm + wm + i * 16) * N + bn + wn + j * 16],
                                        cf[i][j], N, wmma::mem_row_major);
    } else {  // mode 4: fused head
        float* ybuf = sm;
        float* w2s = sm + 128 * 68;
        float* rv = w2s + 192;
        float* cts = rv + 64;
        if (wn < 64) {
#pragma unroll
            for (int i = 0; i < 4; i++)
#pragma unroll
                for (int j = 0; j < 2; j++)
                    wmma::store_matrix_sync(ybuf + (wm + i * 16) * 68 + wn + j * 16,
                                            cf[i][j], 68, wmma::mem_row_major);
        }
        if (tid < 192) w2s[tid] = W2p[tid];
        else if (tid < 195) cts[1 + tid - 192] = b2p[tid - 192];
        else if (tid == 195) cts[0] = bias[0];
        if (tid < 64) rv[tid] = d_rvec[tid];
        __syncthreads();
        if (tid < 128) {
            int row = bm + tid;
            if (row < NN) {
                float a = cts[0];
                float s0 = cts[1], s1 = cts[2], s2 = cts[3];
                const float* yr = ybuf + tid * 68;
#pragma unroll
                for (int f = 0; f < 64; f++) {
                    float v = fmaxf(a * yr[f] + rv[f], 0.f);
                    s0 += v * w2s[f];
                    s1 += v * w2s[64 + f];
                    s2 += v * w2s[128 + f];
                }
                float m = fmaxf(s0, fmaxf(s1, s2));
                float e0 = expf(s0 - m), e1 = expf(s1 - m), e2 = expf(s2 - m);
                float inv = 1.f / (e0 + e1 + e2);
                C[(size_t)row * 3 + 0] = e0 * inv;
                C[(size_t)row * 3 + 1] = e1 * inv;
                C[(size_t)row * 3 + 2] = e2 * inv;
            }
        }
    }
#undef ISSUE
}

// ---------------- cp.async bf16 GEMM (BK=32, 3-stage, split-K capable) --------
// mode 0: fp32 store   mode 2: blockIdx.x==0 -> bf16 pack to d_p2h, else fp32
// mode 3: split-K atomicAdd   mode 5: bias+relu+bf16 pack -> d_h1h
// mode 6: wn<64 -> bf16 pack to d_p3h; wn>=64 -> fp32 store (grid.x must be 1)
__global__ void __launch_bounds__(256, 2) k_tgemmH(
    const __nv_bfloat16* __restrict__ A, const __nv_bfloat16* __restrict__ B,
    float* __restrict__ C, int N, int K, const float* __restrict__ bias, int mode) {
    extern __shared__ float sm[];
    __nv_bfloat16* Asm = (__nv_bfloat16*)sm;
    __nv_bfloat16* Bsm = (__nv_bfloat16*)(sm + 3 * 2560);
    int tid = threadIdx.x;
    int wid = tid >> 5;
    int lane = tid & 31;
    int bm = blockIdx.y * 128;
    int bn = blockIdx.x * 128;
    int wm = (wid >> 2) * 64;
    int wn = (wid & 3) * 32;
    int lrow = tid >> 1;
    int lcol = (tid & 1) * 16;
    int nkz = (K / 32) / gridDim.z;
    int kbase = blockIdx.z * nkz * 32;

    const __nv_bfloat16* Ap = A + (size_t)(bm + lrow) * K + kbase + lcol;
    const __nv_bfloat16* Bp = B + (size_t)(bn + lrow) * K + kbase + lcol;
    unsigned aS = (unsigned)__cvta_generic_to_shared(Asm + lrow * 40 + lcol);
    unsigned bS = (unsigned)__cvta_generic_to_shared(Bsm + lrow * 40 + lcol);

#define ISSUEH(s, koff)                                     \
    do {                                                    \
        unsigned _ao = aS + (s) * 10240;                    \
        unsigned _bo = bS + (s) * 10240;                    \
        CPA(_ao, Ap + (koff)); CPA(_ao + 16, Ap + (koff) + 8); \
        CPA(_bo, Bp + (koff)); CPA(_bo + 16, Bp + (koff) + 8); \
    } while (0)

    wmma::fragment<wmma::accumulator, 16, 16, 16, float> cf[4][2];
#pragma unroll
    for (int i = 0; i < 4; i++)
#pragma unroll
        for (int j = 0; j < 2; j++) wmma::fill_fragment(cf[i][j], 0.f);

    ISSUEH(0, 0); CPCOMMIT();
    if (nkz > 1) { ISSUEH(1, 32); CPCOMMIT(); }
    else CPCOMMIT();

    for (int it = 0; it < nkz; it++) {
        CPWAIT1();
        __syncthreads();
        if (it + 2 < nkz) ISSUEH((it + 2) % 3, (it + 2) * 32);
        CPCOMMIT();
        int buf = it % 3;
        __nv_bfloat16* Ab = Asm + buf * 5120;
        __nv_bfloat16* Bb = Bsm + buf * 5120;
#pragma unroll
        for (int ks = 0; ks < 32; ks += 16) {
            wmma::fragment<wmma::matrix_a, 16, 16, 16, __nv_bfloat16, wmma::row_major> af[4];
            wmma::fragment<wmma::matrix_b, 16, 16, 16, __nv_bfloat16, wmma::col_major> bf[2];
#pragma unroll
            for (int i = 0; i < 4; i++)
                wmma::load_matrix_sync(af[i], Ab + (wm + i * 16) * 40 + ks, 40);
#pragma unroll
            for (int j = 0; j < 2; j++)
                wmma::load_matrix_sync(bf[j], Bb + (wn + j * 16) * 40 + ks, 40);
#pragma unroll
            for (int i = 0; i < 4; i++)
#pragma unroll
                for (int j = 0; j < 2; j++)
                    wmma::mma_sync(cf[i][j], af[i], bf[j], cf[i][j]);
        }
    }
    CPWAIT0();
    __syncthreads();

    bool plain = (mode == 0) || (mode == 2 && blockIdx.x != 0) ||
                 (mode == 6 && wn >= 64);
    if (plain) {
#pragma unroll
        for (int i = 0; i < 4; i++)
#pragma unroll
            for (int j = 0; j < 2; j++)
                wmma::store_matrix_sync(&C[(size_t)(bm + wm + i * 16) * N + bn + wn + j * 16],
                                        cf[i][j], N, wmma::mem_row_major);
    } else if (mode == 2 || mode == 6) {  // bf16 pack (p2h or p3h)
        float* stage = sm + wid * 320;
        int r = lane >> 1, cu = (lane & 1) * 4;
        unsigned int* dst = (mode == 2) ? d_p2h : d_p3h;
        int rowstride = (mode == 2) ? 64 : 32;
#pragma unroll
        for (int i = 0; i < 4; i++)
#pragma unroll
            for (int j = 0; j < 2; j++) {
                wmma::store_matrix_sync(stage, cf[i][j], 20, wmma::mem_row_major);
                __syncwarp();
                const float* sp = stage + r * 20 + cu * 2;
                unsigned int o[4];
#pragma unroll
                for (int t = 0; t < 4; t++) {
                    __nv_bfloat162 h = __floats2bfloat162_rn(sp[2 * t], sp[2 * t + 1]);
                    o[t] = *(unsigned int*)&h;
                }
                *(uint4*)&dst[(size_t)(bm + wm + i * 16 + r) * rowstride +
                              ((wn + j * 16) >> 1) + cu] =
                    make_uint4(o[0], o[1], o[2], o[3]);
                __syncwarp();
            }
    } else if (mode == 3) {
        float* stage = sm + wid * 320;
#pragma unroll
        for (int i = 0; i < 4; i++)
#pragma unroll
            for (int j = 0; j < 2; j++) {
                wmma::store_matrix_sync(stage, cf[i][j], 20, wmma::mem_row_major);
                __syncwarp();
                float* cp = &C[(size_t)(bm + wm + i * 16) * N + bn + wn + j * 16];
#pragma unroll
                for (int e = 0; e < 8; e++) {
                    int idx = lane * 8 + e;
                    int r2 = idx >> 4, c2 = idx & 15;
                    atomicAdd(&cp[(size_t)r2 * N + c2], stage[r2 * 20 + c2]);
                }
                __syncwarp();
            }
    } else {  // mode 5
        float* stage = sm + wid * 320;
        int r = lane >> 1, cu = (lane & 1) * 4;
#pragma unroll
        for (int i = 0; i < 4; i++)
#pragma unroll
            for (int j = 0; j < 2; j++) {
                wmma::store_matrix_sync(stage, cf[i][j], 20, wmma::mem_row_major);
                __syncwarp();
                const float* sp = stage + r * 20 + cu * 2;
                const float* bp = bias + bn + wn + j * 16 + cu * 2;
                unsigned int o[4];
#pragma unroll
                for (int t = 0; t < 4; t++) {
                    float v0 = fmaxf(sp[2 * t] + bp[2 * t], 0.f);
                    float v1 = fmaxf(sp[2 * t + 1] + bp[2 * t + 1], 0.f);
                    __nv_bfloat162 h = __floats2bfloat162_rn(v0, v1);
                    o[t] = *(unsigned int*)&h;
                }
                *(uint4*)&d_h1h[(size_t)(bm + wm + i * 16 + r) * 128 +
                                ((bn + wn + j * 16) >> 1) + cu] =
                    make_uint4(o[0], o[1], o[2], o[3]);
                __syncwarp();
            }
    }
#undef ISSUEH
}

// ---------------- map encoder ----------------
__global__ void k_conv1(const float* __restrict__ in, const float* __restrict__ w,
                        const float* __restrict__ b) {
    int idx = blockIdx.x * blockDim.x + threadIdx.x;
    if (idx >= 256 * 1573) return;
    int oc = idx / 1573, p = idx % 1573;
    int od = p / 121, r = p % 121, oh = r / 11, ow = r % 11;
    const float* wp = w + oc * 75;
    float acc = 0.f;
#pragma unroll
    for (int kd = 0; kd < 3; kd++)
#pragma unroll
        for (int kh = 0; kh < 5; kh++)
#pragma unroll
            for (int kw = 0; kw < 5; kw++)
                acc += in[(od + kd) * 225 + (oh + kh) * 15 + (ow + kw)] *
                       wp[kd * 25 + kh * 5 + kw];
    d_m1[idx] = fmaxf(acc + b[oc], 0.f);
}

__global__ void k_im2col() {
    int k = blockIdx.x * 256 + threadIdx.x;
    int pos = blockIdx.y;
    d_xcolh[(size_t)pos * 6912 + k] = __float2bfloat16(d_m1[d_koff[k] + d_poff[pos]]);
}

__global__ void k_m2fin(const float* __restrict__ cb2) {
    int idx = blockIdx.x * blockDim.x + threadIdx.x;
    if (idx >= 128 * 891) return;
    int oc = idx / 891, pos = idx % 891;
    d_m2[idx] = fmaxf(d_cg[(size_t)pos * 128 + oc] + cb2[oc], 0.f);
}

__global__ void k_wm(const float* __restrict__ Wm) {
    __shared__ float red[256];
    int o = blockIdx.x;
    int chunk = blockIdx.y;
    const int CH = 114048 / 8;
    int base = chunk * CH;
    const float* wr = Wm + (size_t)o * 114048 + base;
    const float* mv = d_m2 + base;
    float s = 0.f;
    for (int i = threadIdx.x * 4; i < CH; i += 256 * 4) {
        float4 a = *(const float4*)(wr + i);
        float4 v = *(const float4*)(mv + i);
        s += a.x * v.x + a.y * v.y + a.z * v.z + a.w * v.w;
    }
    red[threadIdx.x] = s;
    __syncthreads();
    for (int st = 128; st > 0; st >>= 1) {
        if (threadIdx.x < st) red[threadIdx.x] += red[threadIdx.x + st];
        __syncthreads();
    }
    if (threadIdx.x == 0) d_wmpart[chunk][o] = red[0];
}

// ---------------- final stats + rvec ----------------
__global__ void k_finstats(const float* __restrict__ bm, const float* __restrict__ b1) {
    __shared__ float smn[256], smx[256];
    __shared__ float mloc[64];
    int t = threadIdx.x;
    float mn = 3.4e38f, mx = -3.4e38f;
    for (int i = t; i < NBC; i += 256) {
        mn = fminf(mn, d_pmin[i]);
        mx = fmaxf(mx, d_pmax[i]);
    }
    smn[t] = mn; smx[t] = mx;
    __syncthreads();
    for (int st = 128; st > 0; st >>= 1) {
        if (t < st) {
            smn[t] = fminf(smn[t], smn[t + st]);
            smx[t] = fmaxf(smx[t], smx[t + st]);
        }
        __syncthreads();
    }
    float hs1v;
    {
        float lo = smn[0], hi = smx[0];
        float a = 0.35f / (hi - lo);
        hs1v = -lo * a;
        if (t == 0) {
            d_hstats[0] = a;
            d_hstats[1] = hs1v;
        }
    }
    __syncthreads();
    float v = 0.f;
    if (t < 64) {
        v = bm[t];
#pragma unroll
        for (int c = 0; c < 8; c++) v += d_wmpart[c][t];
    }
    smn[t] = (t < 64) ? v : 3.4e38f;
    smx[t] = (t < 64) ? v : -3.4e38f;
    __syncthreads();
    for (int st = 128; st > 0; st >>= 1) {
        if (t < st) {
            smn[t] = fminf(smn[t], smn[t + st]);
            smx[t] = fmaxf(smx[t], smx[t + st]);
        }
        __syncthreads();
    }
    if (t < 64) {
        float lo = smn[0], hi = smx[0];
        float m = 0.65f * (v - lo) / (hi - lo);
        d_mnorm[t] = m;
        mloc[t] = m;
    }
    __syncthreads();
    if (t < 64) {
        float s = b1[t];
        const float* wr = d_w1p + t * 64;
#pragma unroll 8
        for (int k = 0; k < 64; k++) s += wr[k] * (hs1v + mloc[k]);
        d_rvec[t] = s;
    }
}

// ---------------- launch ----------------
extern "C" void kernel_launch(void* const* d_in, const int* in_sizes, int n_in,
                              void* d_out, int out_size) {
    (void)in_sizes; (void)n_in; (void)out_size;
    const float* node = (const float*)d_in[0];
    const int* ei = (const int*)d_in[1];
    const float* mapd = (const float*)d_in[2];
    const float* bl1 = (const float*)d_in[4];
    const float* bl2 = (const float*)d_in[7];
    const float* bl3 = (const float*)d_in[10];
    const float* k1 = (const float*)d_in[12];
    const float* cb1 = (const float*)d_in[13];
    const float* k2 = (const float*)d_in[14];
    const float* cb2 = (const float*)d_in[15];
    const float* Wm = (const float*)d_in[16];
    const float* bm = (const float*)d_in[17];
    const float* b1 = (const float*)d_in[19];
    const float* W2 = (const float*)d_in[20];
    const float* b2 = (const float*)d_in[21];
    float* out = (float*)d_out;

    cudaFuncSetAttribute(k_tgemmA, cudaFuncAttributeMaxDynamicSharedMemorySize, TGA_SMEM);
    cudaFuncSetAttribute(k_tgemmH, cudaFuncAttributeMaxDynamicSharedMemorySize, TGA_SMEM);

    void *p_cnt, *p_cg;
    void *p_mxh, *p_wc1h, *p_h1h, *p_wc2h, *p_pq2, *p_h2h, *p_wc3h, *p_pq3, *p_h3;
    void *p_w1p, *p_xcolh, *p_k2h, *p_hstats;
    cudaGetSymbolAddress(&p_cnt, d_cnt);
    cudaGetSymbolAddress(&p_cg, d_cg);
    cudaGetSymbolAddress(&p_mxh, d_mxh);
    cudaGetSymbolAddress(&p_wc1h, d_wc1h);
    cudaGetSymbolAddress(&p_h1h, d_h1h);
    cudaGetSymbolAddress(&p_wc2h, d_wc2h);
    cudaGetSymbolAddress(&p_pq2, d_pq2);
    cudaGetSymbolAddress(&p_h2h, d_h2h);
    cudaGetSymbolAddress(&p_wc3h, d_wc3h);
    cudaGetSymbolAddress(&p_pq3, d_pq3);
    cudaGetSymbolAddress(&p_h3, d_h3);
    cudaGetSymbolAddress(&p_w1p, d_w1p);
    cudaGetSymbolAddress(&p_xcolh, d_xcolh);
    cudaGetSymbolAddress(&p_k2h, d_k2h);
    cudaGetSymbolAddress(&p_hstats, d_hstats);

    cudaStream_t s2;
    cudaStreamCreateWithFlags(&s2, cudaStreamNonBlocking);
    cudaEvent_t evFork, evJoin;
    cudaEventCreateWithFlags(&evFork, cudaEventDisableTiming);
    cudaEventCreateWithFlags(&evJoin, cudaEventDisableTiming);

    // 1: memset(cnt)  2: memset(cg)  3: packAll
    cudaMemsetAsync(p_cnt, 0, NN * sizeof(int));
    cudaMemsetAsync(p_cg, 0, 896 * 128 * sizeof(float));
    k_packAll<<<447, 256>>>((const float*)d_in[3], (const float*)d_in[5],
                            (const float*)d_in[6], (const float*)d_in[8],
                            (const float*)d_in[9], (const float*)d_in[11],
                            (const float*)d_in[18]);

    // fork conv path onto s2
    cudaEventRecord(evFork, 0);
    cudaStreamWaitEvent(s2, evFork, 0);

    // conv path on s2
    k_packK2<<<(128 * 6912 + 255) / 256, 256, 0, s2>>>(k2);
    k_conv1<<<(256 * 1573 + 255) / 256, 256, 0, s2>>>(mapd, k1, cb1);
    k_im2col<<<dim3(27, 891), 256, 0, s2>>>();
    k_tgemmH<<<dim3(1, 7, 24), 256, TGA_SMEM, s2>>>((const __nv_bfloat16*)p_xcolh,
                                                    (const __nv_bfloat16*)p_k2h,
                                                    (float*)p_cg, 128, 6912,
                                                    nullptr, 3);
    k_m2fin<<<(128 * 891 + 255) / 256, 256, 0, s2>>>(cb2);
    k_wm<<<dim3(64, 8), 256, 0, s2>>>(Wm);
    cudaEventRecord(evJoin, s2);

    // GNN path on main stream
    k_degcnt<<<(NN * 32 + 255) / 256, 256>>>(ei, node);
    k_scan1<<<NB1, 256>>>();
    k_scan3<<<NB1, 256>>>();
    k_scatter<<<(NE + 255) / 256, 256>>>(ei);

    k_aggA<<<(NN * 32 + 255) / 256, 256>>>();
    // GEMM1 (bf16, K=64): bias+relu+bf16 pack -> d_h1h
    k_tgemmH<<<dim3(2, 391, 1), 256, TGA_SMEM>>>((const __nv_bfloat16*)p_mxh,
                                                 (const __nv_bfloat16*)p_wc1h,
                                                 nullptr, 256, 64, bl1, 5);
    // GEMM2 (bf16): p-half -> d_p2h, q-half fp32
    k_tgemmH<<<dim3(2, 391, 1), 256, TGA_SMEM>>>((const __nv_bfloat16*)p_h1h,
                                                 (const __nv_bfloat16*)p_wc2h,
                                                 (float*)p_pq2, 256, 256, nullptr, 2);
    k_aggB<<<(NN * 32 + 255) / 256, 256>>>(bl2);
    // GEMM3 (bf16): p-half -> d_p3h (bf16), q-half fp32 -> pq3
    k_tgemmH<<<dim3(1, 391, 1), 256, TGA_SMEM>>>((const __nv_bfloat16*)p_h2h,
                                                 (const __nv_bfloat16*)p_wc3h,
                                                 (float*)p_pq3, 128, 128, nullptr, 6);
    k_aggC<<<NBC, 256>>>(bl3);

    // join conv path before finstats
    cudaStreamWaitEvent(0, evJoin, 0);
    k_finstats<<<1, 256>>>(bm, b1);
    // GEMM4 (tf32) + fused head
    k_tgemmA<<<dim3(1, 391, 1), 256, TGA_SMEM>>>((const float*)p_h3, (const float*)p_w1p,
                                                 out, 128, 64, (const float*)p_hstats, 4,
                                                 W2, b2);

    cudaEventDestroy(evFork);
    cudaEventDestroy(evJoin);
    cudaStreamDestroy(s2);
}